// round 13
// baseline (speedup 1.0000x reference)
#include <cuda_runtime.h>
#include <cstdint>

// HistPredictor: splat B*K 2D Gaussians onto 128x128 grids, normalize per batch.
// B=256, K=16, grid 128x128 over [-2,2]^2, MIN_SIGMA=0.001.
//
// R13: R11 math (scalar 4-chain geometric recurrence fast path, scalar-EX2
// slow path, lcmax rebase) restructured into two phases:
//   Phase 1: classify all 16 mixtures per warp (live / steep) in one unrolled
//            burst of overlapping ballots -> two warp-uniform bitmasks.
//   Phase 2: iterate ONLY live mixtures via __ffs on the mask; no votes, no
//            dead-mixture setup, uniform branch on the steep bit.

#define KMIX 16

__device__ __forceinline__ float ex2f(float x) {
    float r;
    asm("ex2.approx.f32 %0, %1;" : "=f"(r) : "f"(x));
    return r;
}

__global__ __launch_bounds__(128, 8) __cluster_dims__(4, 1, 1)
void gmm_hist_kernel(const float* __restrict__ mu,
                     const float* __restrict__ sigma,
                     const float* __restrict__ cov12,
                     const float* __restrict__ pi,
                     float* __restrict__ out)
{
    // log2-domain coefficients: e = a2*du^2 + b2*du*dv + c2*dv^2 + (lc - lcmax)
    __shared__ float s_a[KMIX], s_b[KMIX], s_c[KMIX], s_c2[KMIX];
    __shared__ float s_mu[KMIX], s_mv[KMIX], s_lc[KMIX];
    __shared__ float s_R[KMIX], s_S[KMIX], s_S4[KMIX];
    __shared__ float s_red[4];
    __shared__ float s_part[4];

    const int blk = blockIdx.x;
    const int b = blk >> 2;        // batch
    const int q = blk & 3;         // u-quarter == cluster ctarank
    const int t = threadIdx.x;

    const float H   = 4.0f / 127.0f;
    const float L2E = 1.4426950408889634f;

    if (t < KMIX) {
        const int idx = b * KMIX + t;
        float su = fmaxf(sigma[idx * 2 + 0], 0.001f);
        float sv = fmaxf(sigma[idx * 2 + 1], 0.001f);
        float su2 = su * su;
        float sv2 = sv * sv;
        float c11 = su2 + 1e-6f;
        float c22 = sv2 + 1e-6f;
        float off = cov12[idx];
        float det_full = c11 * c22 - off * off;
        // valid = (det_full > 0) & ~isnan(det_full); NaN>0 is false -> covered.
        float ia, ib, ic, det;
        if (det_full > 0.0f) {
            float rdet = 1.0f / det_full;
            ia = c22 * rdet;
            ib = -off * rdet;
            ic = c11 * rdet;
            det = det_full;
        } else {
            ia = 1.0f / su2;
            ib = 0.0f;
            ic = 1.0f / sv2;
            det = su2 * sv2;
        }
        float a2 = -0.5f * L2E * ia;
        float b2 = -L2E * ib;
        float c2 = -0.5f * L2E * ic;   // strictly < 0
        s_a[t]  = a2;
        s_b[t]  = b2;
        s_c[t]  = c2;
        s_c2[t] = 2.0f * c2;
        float R = c2 * (H * H);        // quadratic-in-j coefficient, < 0
        s_R[t]  = R;
        s_S[t]  = -0.5f / R;
        s_S4[t] = ex2f(fmaxf(32.0f * R, -280.0f));  // 4-step ratio decay
        s_mu[t] = mu[idx * 2 + 0];
        s_mv[t] = mu[idx * 2 + 1];
        float coef = pi[idx] / (6.283185307179586f * sqrtf(det + 1e-6f));
        s_lc[t]   = __log2f(coef);     // -inf for coef==0
    }
    __syncthreads();

    // rebase by lcmax (cancels in normalization; improves underflow margin)
    float lcmax = s_lc[0];
#pragma unroll
    for (int k = 1; k < KMIX; k++) lcmax = fmaxf(lcmax, s_lc[k]);

    // Thread t owns u = q*32 + (t>>2), v in [(t&3)*32, +32)
    const int u  = q * 32 + (t >> 2);
    const int v0 = (t & 3) * 32;
    const float uc    = -2.0f + (float)u  * H;
    const float vbase = -2.0f + (float)v0 * H;

    // ---------------- Phase 1: classify all mixtures (warp-uniform masks) ---
    unsigned live_mask = 0u, steep_mask = 0u;
#pragma unroll
    for (int k = 0; k < KMIX; k++) {
        const float R = s_R[k];
        const float du  = uc    - s_mu[k];
        const float dv0 = vbase - s_mv[k];
        const float Q = fmaf(s_c2[k], dv0, s_b[k] * du) * H;
        const float P = fmaf(fmaf(s_b[k], dv0, s_a[k] * du), du,
                             fmaf(s_c[k] * dv0, dv0, s_lc[k] - lcmax));
        float jc = fminf(fmaxf(Q * s_S[k], 0.0f), 31.0f);
        float ev = fmaf(jc, fmaf(R, jc, Q), P);           // row max (concave)
        float e31 = fmaf(31.0f, fmaf(R, 31.0f, Q), P);
        bool lv = (ev >= -18.0f);
        bool sp = lv && ((ev - fminf(P, e31)) > 100.0f);
        if (__ballot_sync(0xffffffffu, lv)) live_mask  |= (1u << k);
        if (__ballot_sync(0xffffffffu, sp)) steep_mask |= (1u << k);
    }

    float acc[32];
#pragma unroll
    for (int j = 0; j < 32; j++) acc[j] = 0.0f;

    // ---------------- Phase 2: process only live mixtures -------------------
    while (live_mask) {
        const int k = __ffs(live_mask) - 1;
        live_mask &= live_mask - 1;

        const float R = s_R[k];
        const float du  = uc    - s_mu[k];
        const float dv0 = vbase - s_mv[k];
        const float Q = fmaf(s_c2[k], dv0, s_b[k] * du) * H;
        const float P = fmaf(fmaf(s_b[k], dv0, s_a[k] * du), du,
                             fmaf(s_c[k] * dv0, dv0, s_lc[k] - lcmax));

        if ((steep_mask >> k) & 1u) {
            // ---- slow path (steep/narrow rows): scalar EX2 per point -------
#pragma unroll
            for (int j = 0; j < 32; j++) {
                const float jf = (float)j;
                float e = fmaf(jf, fmaf(R, jf, Q), P);
                acc[j] += ex2f(e);
            }
        } else {
            // ---- fast path: 4 interleaved geometric chains ------------------
            // seeds: g_c = 2^e(c); T_c = 2^(e(c+4)-e(c)) = 2^(4Q + R(8c+16))
            const float S4 = s_S4[k];
            float g0 = ex2f(P);
            float g1 = ex2f(P + Q + R);
            float g2 = ex2f(fmaf(2.0f, fmaf(R, 2.0f, Q), P));
            float g3 = ex2f(fmaf(3.0f, fmaf(R, 3.0f, Q), P));
            const float fourQ = 4.0f * Q;
            // clamp ratio exponents so dead lanes (g underflowed to 0) stay 0
            float T0 = ex2f(fminf(fmaf(16.0f, R, fourQ), 120.0f));
            float T1 = ex2f(fminf(fmaf(24.0f, R, fourQ), 120.0f));
            float T2 = ex2f(fminf(fmaf(32.0f, R, fourQ), 120.0f));
            float T3 = ex2f(fminf(fmaf(40.0f, R, fourQ), 120.0f));
#pragma unroll
            for (int i = 0; i < 8; i++) {
                acc[4 * i + 0] += g0;
                acc[4 * i + 1] += g1;
                acc[4 * i + 2] += g2;
                acc[4 * i + 3] += g3;
                g0 *= T0;  g1 *= T1;  g2 *= T2;  g3 *= T3;
                T0 *= S4;  T1 *= S4;  T2 *= S4;  T3 *= S4;
            }
        }
    }

    // CTA partial sum (this u-quarter, rebased domain)
    float s = 0.0f;
#pragma unroll
    for (int j = 0; j < 32; j++) s += acc[j];
#pragma unroll
    for (int o = 16; o > 0; o >>= 1) s += __shfl_xor_sync(0xffffffffu, s, o);
    const int warp = t >> 5;
    const int lane = t & 31;
    if (lane == 0) s_red[warp] = s;
    __syncthreads();

    // Thread 0 scatters this CTA's partial into slot q of all 4 cluster CTAs.
    if (t == 0) {
        float mysum = s_red[0] + s_red[1] + s_red[2] + s_red[3];
        uint32_t laddr;
        asm("{ .reg .u64 tmp; cvta.to.shared.u64 tmp, %1; cvt.u32.u64 %0, tmp; }"
            : "=r"(laddr) : "l"(&s_part[q]));
#pragma unroll
        for (int r = 0; r < 4; r++) {
            uint32_t raddr;
            asm("mapa.shared::cluster.u32 %0, %1, %2;" : "=r"(raddr) : "r"(laddr), "r"(r));
            asm volatile("st.shared::cluster.f32 [%0], %1;" :: "r"(raddr), "f"(mysum)
                         : "memory");
        }
    }
    // Cluster barrier: arrive(release) orders the DSMEM stores; wait(acquire)
    // makes all 4 partials visible in local s_part.
    asm volatile("barrier.cluster.arrive.aligned;" ::: "memory");
    asm volatile("barrier.cluster.wait.aligned;"   ::: "memory");

    const float tot = (s_part[0] + s_part[1]) + (s_part[2] + s_part[3]);
    const float inv = (tot > 0.0f) ? (1.0f / tot) : 1.0f;   // 2^lcmax cancels

    // normalized store (coalesced float4)
    float* op = out + (size_t)b * 16384 + (size_t)u * 128 + v0;
#pragma unroll
    for (int j = 0; j < 32; j += 4) {
        float4 w = make_float4(acc[j] * inv, acc[j + 1] * inv,
                               acc[j + 2] * inv, acc[j + 3] * inv);
        *reinterpret_cast<float4*>(op + j) = w;
    }
}

extern "C" void kernel_launch(void* const* d_in, const int* in_sizes, int n_in,
                              void* d_out, int out_size)
{
    const float* mu    = (const float*)d_in[0];
    const float* sigma = (const float*)d_in[1];
    const float* cov12 = (const float*)d_in[2];
    const float* pi    = (const float*)d_in[3];
    float* out = (float*)d_out;
    gmm_hist_kernel<<<1024, 128>>>(mu, sigma, cov12, pi, out);
}

// round 14
// speedup vs baseline: 1.0259x; 1.0259x over previous
#include <cuda_runtime.h>
#include <cstdint>

// HistPredictor: splat B*K 2D Gaussians onto 128x128 grids, normalize per batch.
// B=256, K=16, grid 128x128 over [-2,2]^2, MIN_SIGMA=0.001.
//
// R14: per-LANE mixture compaction. Each lane builds its own live-k bitmask
// (vertex max of the row quadratic >= -18 in rebased log2 domain); the main
// loop runs while any lane has work, each lane on ITS OWN next k (divergent
// LDS of per-k params; sentinel k=16 contributes exact 0). Uniform inner body:
// 2 FFMA-imm + EX2 + FADD per point, full f32. 4-CTA cluster + DSMEM norm.

#define KMIX 16

__device__ __forceinline__ float ex2f(float x) {
    float r;
    asm("ex2.approx.f32 %0, %1;" : "=f"(r) : "f"(x));
    return r;
}

__global__ __launch_bounds__(128, 8) __cluster_dims__(4, 1, 1)
void gmm_hist_kernel(const float* __restrict__ mu,
                     const float* __restrict__ sigma,
                     const float* __restrict__ cov12,
                     const float* __restrict__ pi,
                     float* __restrict__ out)
{
    // 17 entries: k=16 is a sentinel giving exact-zero contribution.
    __shared__ float s_a[17], s_b[17], s_c[17], s_c2[17];
    __shared__ float s_mu[17], s_mv[17], s_lc[17];
    __shared__ float s_R[17], s_S[17];
    __shared__ float s_red[4];
    __shared__ float s_part[4];

    const int blk = blockIdx.x;
    const int b = blk >> 2;        // batch
    const int q = blk & 3;         // u-quarter == cluster ctarank
    const int t = threadIdx.x;

    const float H   = 4.0f / 127.0f;
    const float L2E = 1.4426950408889634f;

    if (t < KMIX) {
        const int idx = b * KMIX + t;
        float su = fmaxf(sigma[idx * 2 + 0], 0.001f);
        float sv = fmaxf(sigma[idx * 2 + 1], 0.001f);
        float su2 = su * su;
        float sv2 = sv * sv;
        float c11 = su2 + 1e-6f;
        float c22 = sv2 + 1e-6f;
        float off = cov12[idx];
        float det_full = c11 * c22 - off * off;
        // valid = (det_full > 0) & ~isnan(det_full); NaN>0 is false -> covered.
        float ia, ib, ic, det;
        if (det_full > 0.0f) {
            float rdet = 1.0f / det_full;
            ia = c22 * rdet;
            ib = -off * rdet;
            ic = c11 * rdet;
            det = det_full;
        } else {
            ia = 1.0f / su2;
            ib = 0.0f;
            ic = 1.0f / sv2;
            det = su2 * sv2;
        }
        float a2 = -0.5f * L2E * ia;
        float b2 = -L2E * ib;
        float c2 = -0.5f * L2E * ic;   // strictly < 0
        s_a[t]  = a2;
        s_b[t]  = b2;
        s_c[t]  = c2;
        s_c2[t] = 2.0f * c2;
        float R = c2 * (H * H);        // quadratic-in-j coefficient, < 0
        s_R[t]  = R;
        s_S[t]  = -0.5f / R;
        s_mu[t] = mu[idx * 2 + 0];
        s_mv[t] = mu[idx * 2 + 1];
        float coef = pi[idx] / (6.283185307179586f * sqrtf(det + 1e-6f));
        s_lc[t]   = __log2f(coef);     // -inf for coef==0
    } else if (t == KMIX) {
        // sentinel: zero coefficients, astronomically negative lc -> ex2 -> 0
        s_a[16] = 0.0f; s_b[16] = 0.0f; s_c[16] = 0.0f; s_c2[16] = 0.0f;
        s_mu[16] = 0.0f; s_mv[16] = 0.0f;
        s_R[16] = 0.0f; s_S[16] = 0.0f;
        s_lc[16] = -1e30f;
    }
    __syncthreads();

    // rebase by lcmax (cancels in normalization; sentinel excluded)
    float lcmax = s_lc[0];
#pragma unroll
    for (int k = 1; k < KMIX; k++) lcmax = fmaxf(lcmax, s_lc[k]);

    // Thread t owns u = q*32 + (t>>2), v in [(t&3)*32, +32)
    const int u  = q * 32 + (t >> 2);
    const int v0 = (t & 3) * 32;
    const float uc    = -2.0f + (float)u  * H;
    const float vbase = -2.0f + (float)v0 * H;

    // ---- per-LANE classification: build this lane's live-k bitmask ---------
    unsigned m = 0u;
#pragma unroll
    for (int k = 0; k < KMIX; k++) {
        const float R = s_R[k];
        const float du  = uc    - s_mu[k];
        const float dv0 = vbase - s_mv[k];
        const float Q = fmaf(s_c2[k], dv0, s_b[k] * du) * H;
        const float P = fmaf(fmaf(s_b[k], dv0, s_a[k] * du), du,
                             fmaf(s_c[k] * dv0, dv0, s_lc[k] - lcmax));
        float jc = fminf(fmaxf(Q * s_S[k], 0.0f), 31.0f);
        float ev = fmaf(jc, fmaf(R, jc, Q), P);   // row max (concave); NaN->skip
        if (ev >= -18.0f) m |= (1u << k);
    }

    float acc[32];
#pragma unroll
    for (int j = 0; j < 32; j++) acc[j] = 0.0f;

    // ---- main loop: each lane consumes its own live list --------------------
    while (__any_sync(0xffffffffu, m != 0u)) {
        const int k = (m != 0u) ? (__ffs((int)m) - 1) : 16;   // 16 = sentinel
        m &= m - 1u;                                          // 0 stays 0

        const float R = s_R[k];
        const float du  = uc    - s_mu[k];
        const float dv0 = vbase - s_mv[k];
        const float Q = fmaf(s_c2[k], dv0, s_b[k] * du) * H;
        const float P = fmaf(fmaf(s_b[k], dv0, s_a[k] * du), du,
                             fmaf(s_c[k] * dv0, dv0, s_lc[k] - lcmax));

        // dependency-free direct evaluation: j as immediates (FFMA-imm)
#pragma unroll
        for (int j = 0; j < 32; j++) {
            const float jf = (float)j;
            float e = fmaf(jf, fmaf(R, jf, Q), P);
            acc[j] += ex2f(e);                    // sentinel: ex2(-1e30) = 0
        }
    }

    // CTA partial sum (this u-quarter, rebased domain)
    float s = 0.0f;
#pragma unroll
    for (int j = 0; j < 32; j++) s += acc[j];
#pragma unroll
    for (int o = 16; o > 0; o >>= 1) s += __shfl_xor_sync(0xffffffffu, s, o);
    const int warp = t >> 5;
    const int lane = t & 31;
    if (lane == 0) s_red[warp] = s;
    __syncthreads();

    // Thread 0 scatters this CTA's partial into slot q of all 4 cluster CTAs.
    if (t == 0) {
        float mysum = s_red[0] + s_red[1] + s_red[2] + s_red[3];
        uint32_t laddr;
        asm("{ .reg .u64 tmp; cvta.to.shared.u64 tmp, %1; cvt.u32.u64 %0, tmp; }"
            : "=r"(laddr) : "l"(&s_part[q]));
#pragma unroll
        for (int r = 0; r < 4; r++) {
            uint32_t raddr;
            asm("mapa.shared::cluster.u32 %0, %1, %2;" : "=r"(raddr) : "r"(laddr), "r"(r));
            asm volatile("st.shared::cluster.f32 [%0], %1;" :: "r"(raddr), "f"(mysum)
                         : "memory");
        }
    }
    // Cluster barrier: arrive(release) orders the DSMEM stores; wait(acquire)
    // makes all 4 partials visible in local s_part.
    asm volatile("barrier.cluster.arrive.aligned;" ::: "memory");
    asm volatile("barrier.cluster.wait.aligned;"   ::: "memory");

    const float tot = (s_part[0] + s_part[1]) + (s_part[2] + s_part[3]);
    const float inv = (tot > 0.0f) ? (1.0f / tot) : 1.0f;   // 2^lcmax cancels

    // normalized store (coalesced float4)
    float* op = out + (size_t)b * 16384 + (size_t)u * 128 + v0;
#pragma unroll
    for (int j = 0; j < 32; j += 4) {
        float4 w = make_float4(acc[j] * inv, acc[j + 1] * inv,
                               acc[j + 2] * inv, acc[j + 3] * inv);
        *reinterpret_cast<float4*>(op + j) = w;
    }
}

extern "C" void kernel_launch(void* const* d_in, const int* in_sizes, int n_in,
                              void* d_out, int out_size)
{
    const float* mu    = (const float*)d_in[0];
    const float* sigma = (const float*)d_in[1];
    const float* cov12 = (const float*)d_in[2];
    const float* pi    = (const float*)d_in[3];
    float* out = (float*)d_out;
    gmm_hist_kernel<<<1024, 128>>>(mu, sigma, cov12, pi, out);
}

// round 15
// speedup vs baseline: 1.1001x; 1.0723x over previous
#include <cuda_runtime.h>
#include <cstdint>

// HistPredictor: splat B*K 2D Gaussians onto 128x128 grids, normalize per batch.
// B=256, K=16, grid 128x128 over [-2,2]^2, MIN_SIGMA=0.001.
//
// R15: square warp footprint for maximal skip leverage. Warp = 32u x 32v tile
// (lane = u-row, warp = v-window); one vertex eval + one ballot per mixture
// (R6's skip), R6's minimal inner loop (2 FFMA-imm + EX2 + FADD, full f32).
// Stores staged through smem for coalescing. 4-CTA cluster + DSMEM norm.

#define KMIX 16
#define HSTRIDE 132   // padded smem row stride (floats), 16B-aligned rows

__device__ __forceinline__ float ex2f(float x) {
    float r;
    asm("ex2.approx.f32 %0, %1;" : "=f"(r) : "f"(x));
    return r;
}

__global__ __launch_bounds__(128, 8) __cluster_dims__(4, 1, 1)
void gmm_hist_kernel(const float* __restrict__ mu,
                     const float* __restrict__ sigma,
                     const float* __restrict__ cov12,
                     const float* __restrict__ pi,
                     float* __restrict__ out)
{
    // log2-domain coefficients: e = a2*du^2 + b2*du*dv + c2*dv^2 + (lc - lcmax)
    __shared__ float s_a[KMIX], s_b[KMIX], s_c[KMIX], s_c2[KMIX];
    __shared__ float s_mu[KMIX], s_mv[KMIX], s_lc[KMIX];
    __shared__ float s_R[KMIX], s_S[KMIX];
    __shared__ float s_red[4];
    __shared__ float s_part[4];
    __shared__ float s_hist[32 * HSTRIDE];   // 32 u-rows x 128 v (padded)

    const int blk = blockIdx.x;
    const int b = blk >> 2;        // batch
    const int q = blk & 3;         // u-quarter == cluster ctarank
    const int t = threadIdx.x;
    const int w    = t >> 5;       // warp -> v-window
    const int lane = t & 31;       // lane -> u-row within quarter

    const float H   = 4.0f / 127.0f;
    const float L2E = 1.4426950408889634f;

    if (t < KMIX) {
        const int idx = b * KMIX + t;
        float su = fmaxf(sigma[idx * 2 + 0], 0.001f);
        float sv = fmaxf(sigma[idx * 2 + 1], 0.001f);
        float su2 = su * su;
        float sv2 = sv * sv;
        float c11 = su2 + 1e-6f;
        float c22 = sv2 + 1e-6f;
        float off = cov12[idx];
        float det_full = c11 * c22 - off * off;
        // valid = (det_full > 0) & ~isnan(det_full); NaN>0 is false -> covered.
        float ia, ib, ic, det;
        if (det_full > 0.0f) {
            float rdet = 1.0f / det_full;
            ia = c22 * rdet;
            ib = -off * rdet;
            ic = c11 * rdet;
            det = det_full;
        } else {
            ia = 1.0f / su2;
            ib = 0.0f;
            ic = 1.0f / sv2;
            det = su2 * sv2;
        }
        float a2 = -0.5f * L2E * ia;
        float b2 = -L2E * ib;
        float c2 = -0.5f * L2E * ic;   // strictly < 0
        s_a[t]  = a2;
        s_b[t]  = b2;
        s_c[t]  = c2;
        s_c2[t] = 2.0f * c2;
        float R = c2 * (H * H);        // quadratic-in-j coefficient, < 0
        s_R[t]  = R;
        s_S[t]  = -0.5f / R;
        s_mu[t] = mu[idx * 2 + 0];
        s_mv[t] = mu[idx * 2 + 1];
        float coef = pi[idx] / (6.283185307179586f * sqrtf(det + 1e-6f));
        s_lc[t]   = __log2f(coef);     // -inf for coef==0
    }
    __syncthreads();

    // rebase by lcmax (cancels in normalization)
    float lcmax = s_lc[0];
#pragma unroll
    for (int k = 1; k < KMIX; k++) lcmax = fmaxf(lcmax, s_lc[k]);

    // lane -> u-row of this quarter; warp -> 32-wide v window
    const int u  = q * 32 + lane;
    const int v0 = w * 32;
    const float uc    = -2.0f + (float)u  * H;
    const float vbase = -2.0f + (float)v0 * H;

    float acc[32];
#pragma unroll
    for (int j = 0; j < 32; j++) acc[j] = 0.0f;

#pragma unroll 1
    for (int k = 0; k < KMIX; k++) {
        const float du  = uc    - s_mu[k];
        const float dv0 = vbase - s_mv[k];
        // e(j) = P' + Q*j + R*j^2,  dv = dv0 + j*H,  P' includes lc - lcmax
        const float R = s_R[k];
        const float Q = fmaf(s_c2[k], dv0, s_b[k] * du) * H;
        const float P = fmaf(fmaf(s_b[k], dv0, s_a[k] * du), du,
                             fmaf(s_c[k] * dv0, dv0, s_lc[k] - lcmax));

        // warp-uniform skip: max of concave e over j in [0,31] vs -18
        // (square 32u x 32v footprint -> much smaller warp union than 8u x 128v)
        float jc = fminf(fmaxf(Q * s_S[k], 0.0f), 31.0f);
        float ev = fmaf(jc, fmaf(R, jc, Q), P);
        if (__ballot_sync(0xffffffffu, ev >= -18.0f) == 0u) continue;

        // dependency-free direct evaluation: j as immediates (FFMA-imm)
#pragma unroll
        for (int j = 0; j < 32; j++) {
            const float jf = (float)j;
            float e = fmaf(jf, fmaf(R, jf, Q), P);   // 2 x FFMA (imm multiplier)
            acc[j] += ex2f(e);                       // MUFU.EX2 + FADD
        }
    }

    // stage tile into smem: lane = u-row, cols [v0, v0+32)
    {
        float* hp = s_hist + lane * HSTRIDE + v0;
#pragma unroll
        for (int j = 0; j < 32; j += 4) {
            *reinterpret_cast<float4*>(hp + j) =
                make_float4(acc[j], acc[j + 1], acc[j + 2], acc[j + 3]);
        }
    }

    // CTA partial sum (this u-quarter, rebased domain)
    float s = 0.0f;
#pragma unroll
    for (int j = 0; j < 32; j++) s += acc[j];
#pragma unroll
    for (int o = 16; o > 0; o >>= 1) s += __shfl_xor_sync(0xffffffffu, s, o);
    if (lane == 0) s_red[w] = s;
    __syncthreads();

    // Thread 0 scatters this CTA's partial into slot q of all 4 cluster CTAs.
    if (t == 0) {
        float mysum = s_red[0] + s_red[1] + s_red[2] + s_red[3];
        uint32_t laddr;
        asm("{ .reg .u64 tmp; cvta.to.shared.u64 tmp, %1; cvt.u32.u64 %0, tmp; }"
            : "=r"(laddr) : "l"(&s_part[q]));
#pragma unroll
        for (int r = 0; r < 4; r++) {
            uint32_t raddr;
            asm("mapa.shared::cluster.u32 %0, %1, %2;" : "=r"(raddr) : "r"(laddr), "r"(r));
            asm volatile("st.shared::cluster.f32 [%0], %1;" :: "r"(raddr), "f"(mysum)
                         : "memory");
        }
    }
    // Cluster barrier: orders DSMEM stores + makes all 4 partials visible;
    // doubles as the CTA barrier protecting s_hist for the read below.
    asm volatile("barrier.cluster.arrive.aligned;" ::: "memory");
    asm volatile("barrier.cluster.wait.aligned;"   ::: "memory");

    const float tot = (s_part[0] + s_part[1]) + (s_part[2] + s_part[3]);
    const float inv = (tot > 0.0f) ? (1.0f / tot) : 1.0f;   // 2^lcmax cancels

    // coalesced normalized store: thread t -> row (t>>2), v-chunk (t&3)*32
    {
        const int r  = t >> 2;
        const int vc = (t & 3) * 32;
        const float* hp = s_hist + r * HSTRIDE + vc;
        float* op = out + (size_t)b * 16384 + (size_t)(q * 32 + r) * 128 + vc;
#pragma unroll
        for (int p = 0; p < 8; p++) {
            float4 x = *reinterpret_cast<const float4*>(hp + 4 * p);
            x.x *= inv; x.y *= inv; x.z *= inv; x.w *= inv;
            *reinterpret_cast<float4*>(op + 4 * p) = x;
        }
    }
}

extern "C" void kernel_launch(void* const* d_in, const int* in_sizes, int n_in,
                              void* d_out, int out_size)
{
    const float* mu    = (const float*)d_in[0];
    const float* sigma = (const float*)d_in[1];
    const float* cov12 = (const float*)d_in[2];
    const float* pi    = (const float*)d_in[3];
    float* out = (float*)d_out;
    gmm_hist_kernel<<<1024, 128>>>(mu, sigma, cov12, pi, out);
}

// round 16
// speedup vs baseline: 1.2076x; 1.0977x over previous
#include <cuda_runtime.h>
#include <cstdint>

// HistPredictor: splat B*K 2D Gaussians onto 128x128 grids, normalize per batch.
// B=256, K=16, grid 128x128 over [-2,2]^2, MIN_SIGMA=0.001.
//
// R16: pipe-balanced geometric recurrence. Per mixture: 8 chains (stride 8,
// 4 steps), seeded by 16 EX2s -> MUFU ~128 cyc/k/warp, chain work 40 FMUL +
// 32 FADD -> fma ~144 cyc/k/warp (balanced; R11 was fma-bound at ~192,
// R6 MUFU-bound at ~256). Chains in 2 register-groups of 4. Span<=100 warp
// guard (overflow-free), scalar-EX2 slow path for steep rows (e<=0 rebased).

#define KMIX 16

__device__ __forceinline__ float ex2f(float x) {
    float r;
    asm("ex2.approx.f32 %0, %1;" : "=f"(r) : "f"(x));
    return r;
}

__global__ __launch_bounds__(128, 8) __cluster_dims__(4, 1, 1)
void gmm_hist_kernel(const float* __restrict__ mu,
                     const float* __restrict__ sigma,
                     const float* __restrict__ cov12,
                     const float* __restrict__ pi,
                     float* __restrict__ out)
{
    // log2-domain coefficients: e = a2*du^2 + b2*du*dv + c2*dv^2 + (lc - lcmax)
    __shared__ float s_a[KMIX], s_b[KMIX], s_c[KMIX], s_c2[KMIX];
    __shared__ float s_mu[KMIX], s_mv[KMIX], s_lc[KMIX];
    __shared__ float s_R[KMIX], s_S[KMIX], s_S128[KMIX];
    __shared__ float s_red[4];
    __shared__ float s_part[4];

    const int blk = blockIdx.x;
    const int b = blk >> 2;        // batch
    const int q = blk & 3;         // u-quarter == cluster ctarank
    const int t = threadIdx.x;

    const float H   = 4.0f / 127.0f;
    const float L2E = 1.4426950408889634f;

    if (t < KMIX) {
        const int idx = b * KMIX + t;
        float su = fmaxf(sigma[idx * 2 + 0], 0.001f);
        float sv = fmaxf(sigma[idx * 2 + 1], 0.001f);
        float su2 = su * su;
        float sv2 = sv * sv;
        float c11 = su2 + 1e-6f;
        float c22 = sv2 + 1e-6f;
        float off = cov12[idx];
        float det_full = c11 * c22 - off * off;
        // valid = (det_full > 0) & ~isnan(det_full); NaN>0 is false -> covered.
        float ia, ib, ic, det;
        if (det_full > 0.0f) {
            float rdet = 1.0f / det_full;
            ia = c22 * rdet;
            ib = -off * rdet;
            ic = c11 * rdet;
            det = det_full;
        } else {
            ia = 1.0f / su2;
            ib = 0.0f;
            ic = 1.0f / sv2;
            det = su2 * sv2;
        }
        float a2 = -0.5f * L2E * ia;
        float b2 = -L2E * ib;
        float c2 = -0.5f * L2E * ic;   // strictly < 0
        s_a[t]  = a2;
        s_b[t]  = b2;
        s_c[t]  = c2;
        s_c2[t] = 2.0f * c2;
        float R = c2 * (H * H);        // quadratic-in-j coefficient, < 0
        s_R[t]  = R;
        s_S[t]  = -0.5f / R;
        s_S128[t] = ex2f(fmaxf(128.0f * R, -280.0f));  // stride-8 step decay
        s_mu[t] = mu[idx * 2 + 0];
        s_mv[t] = mu[idx * 2 + 1];
        float coef = pi[idx] / (6.283185307179586f * sqrtf(det + 1e-6f));
        s_lc[t]   = __log2f(coef);     // -inf for coef==0
    }
    __syncthreads();

    // rebase by lcmax: all exponents <= 0; 2^lcmax cancels in normalization
    float lcmax = s_lc[0];
#pragma unroll
    for (int k = 1; k < KMIX; k++) lcmax = fmaxf(lcmax, s_lc[k]);

    // Thread t owns u = q*32 + (t>>2), v in [(t&3)*32, +32)
    const int u  = q * 32 + (t >> 2);
    const int v0 = (t & 3) * 32;
    const float uc    = -2.0f + (float)u  * H;
    const float vbase = -2.0f + (float)v0 * H;

    float acc[32];
#pragma unroll
    for (int j = 0; j < 32; j++) acc[j] = 0.0f;

#pragma unroll 1
    for (int k = 0; k < KMIX; k++) {
        const float du  = uc    - s_mu[k];
        const float dv0 = vbase - s_mv[k];
        // e(j) = P' + Q*j + R*j^2,  dv = dv0 + j*H,  P' includes lc - lcmax
        const float R = s_R[k];
        const float Q = fmaf(s_c2[k], dv0, s_b[k] * du) * H;
        const float P = fmaf(fmaf(s_b[k], dv0, s_a[k] * du), du,
                             fmaf(s_c[k] * dv0, dv0, s_lc[k] - lcmax));

        // warp-uniform skip: max of concave e over j in [0,31] vs -18
        float jc = fminf(fmaxf(Q * s_S[k], 0.0f), 31.0f);
        float ev = fmaf(jc, fmaf(R, jc, Q), P);
        if (__ballot_sync(0xffffffffu, ev >= -18.0f) == 0u) continue;

        // span test: recurrence path only if every live lane is "shallow"
        float e31 = fmaf(31.0f, fmaf(R, 31.0f, Q), P);
        bool lane_steep = (ev >= -18.0f) && ((ev - fminf(P, e31)) > 100.0f);

        if (__any_sync(0xffffffffu, lane_steep)) {
            // ---- slow path (rare, steep/narrow rows): scalar EX2 per point --
            // safe unconditionally: rebased e <= 0, underflow -> 0
#pragma unroll
            for (int j = 0; j < 32; j++) {
                const float jf = (float)j;
                float e = fmaf(jf, fmaf(R, jf, Q), P);
                acc[j] += ex2f(e);
            }
        } else {
            // ---- fast path: 8 stride-8 chains x 4 steps, 2 groups of 4 -----
            // chain c covers j = c, c+8, c+16, c+24;
            // g_c = 2^e(c);  T_c = 2^(e(c+8)-e(c)) = 2^(8Q + R(16c+64));
            // step decay S = 2^(128R) (warp-uniform, smem).
            const float S = s_S128[k];
            const float eightQ = 8.0f * Q;
#pragma unroll
            for (int grp = 0; grp < 2; grp++) {
                const int c0 = grp * 4;
                const float f0 = (float)(c0 + 0);
                const float f1 = (float)(c0 + 1);
                const float f2 = (float)(c0 + 2);
                const float f3 = (float)(c0 + 3);
                float g0 = ex2f(fmaf(f0, fmaf(R, f0, Q), P));
                float g1 = ex2f(fmaf(f1, fmaf(R, f1, Q), P));
                float g2 = ex2f(fmaf(f2, fmaf(R, f2, Q), P));
                float g3 = ex2f(fmaf(f3, fmaf(R, f3, Q), P));
                // clamp T exponents so dead lanes (g underflowed to 0) stay 0
                float T0 = ex2f(fminf(fmaf(16.0f * f0 + 64.0f, R, eightQ), 120.0f));
                float T1 = ex2f(fminf(fmaf(16.0f * f1 + 64.0f, R, eightQ), 120.0f));
                float T2 = ex2f(fminf(fmaf(16.0f * f2 + 64.0f, R, eightQ), 120.0f));
                float T3 = ex2f(fminf(fmaf(16.0f * f3 + 64.0f, R, eightQ), 120.0f));
#pragma unroll
                for (int st = 0; st < 4; st++) {
                    acc[c0 + 0 + 8 * st] += g0;
                    acc[c0 + 1 + 8 * st] += g1;
                    acc[c0 + 2 + 8 * st] += g2;
                    acc[c0 + 3 + 8 * st] += g3;
                    if (st < 3) {
                        g0 *= T0;  g1 *= T1;  g2 *= T2;  g3 *= T3;
                        if (st < 2) { T0 *= S;  T1 *= S;  T2 *= S;  T3 *= S; }
                    }
                }
            }
        }
    }

    // CTA partial sum (this u-quarter, rebased domain)
    float s = 0.0f;
#pragma unroll
    for (int j = 0; j < 32; j++) s += acc[j];
#pragma unroll
    for (int o = 16; o > 0; o >>= 1) s += __shfl_xor_sync(0xffffffffu, s, o);
    const int warp = t >> 5;
    const int lane = t & 31;
    if (lane == 0) s_red[warp] = s;
    __syncthreads();

    // Thread 0 scatters this CTA's partial into slot q of all 4 cluster CTAs.
    if (t == 0) {
        float mysum = s_red[0] + s_red[1] + s_red[2] + s_red[3];
        uint32_t laddr;
        asm("{ .reg .u64 tmp; cvta.to.shared.u64 tmp, %1; cvt.u32.u64 %0, tmp; }"
            : "=r"(laddr) : "l"(&s_part[q]));
#pragma unroll
        for (int r = 0; r < 4; r++) {
            uint32_t raddr;
            asm("mapa.shared::cluster.u32 %0, %1, %2;" : "=r"(raddr) : "r"(laddr), "r"(r));
            asm volatile("st.shared::cluster.f32 [%0], %1;" :: "r"(raddr), "f"(mysum)
                         : "memory");
        }
    }
    // Cluster barrier: arrive(release) orders the DSMEM stores; wait(acquire)
    // makes all 4 partials visible in local s_part.
    asm volatile("barrier.cluster.arrive.aligned;" ::: "memory");
    asm volatile("barrier.cluster.wait.aligned;"   ::: "memory");

    const float tot = (s_part[0] + s_part[1]) + (s_part[2] + s_part[3]);
    const float inv = (tot > 0.0f) ? (1.0f / tot) : 1.0f;   // 2^lcmax cancels

    // normalized store (coalesced float4)
    float* op = out + (size_t)b * 16384 + (size_t)u * 128 + v0;
#pragma unroll
    for (int j = 0; j < 32; j += 4) {
        float4 w = make_float4(acc[j] * inv, acc[j + 1] * inv,
                               acc[j + 2] * inv, acc[j + 3] * inv);
        *reinterpret_cast<float4*>(op + j) = w;
    }
}

extern "C" void kernel_launch(void* const* d_in, const int* in_sizes, int n_in,
                              void* d_out, int out_size)
{
    const float* mu    = (const float*)d_in[0];
    const float* sigma = (const float*)d_in[1];
    const float* cov12 = (const float*)d_in[2];
    const float* pi    = (const float*)d_in[3];
    float* out = (float*)d_out;
    gmm_hist_kernel<<<1024, 128>>>(mu, sigma, cov12, pi, out);
}